// round 5
// baseline (speedup 1.0000x reference)
#include <cuda_runtime.h>
#include <cuda_bf16.h>
#include <math.h>

// Problem constants
#define T_TOK   16384      // B*S tokens
#define HDIM    1024
#define MDIM    2048
#define NEXP    16
#define TOPK    2
#define NASSIGN (T_TOK * TOPK)   // 32768

// ---------------- scratch (device globals; no allocation allowed) ----------
static __device__ float g_H[(size_t)NASSIGN * MDIM];   // 256 MB: relu(x W1 + b1) rows
static __device__ float g_Y[(size_t)NASSIGN * HDIM];   // 128 MB: h W2 + b2 rows
static __device__ int   g_counts[NEXP];
static __device__ int   g_offsets[NEXP];
static __device__ int   g_cursor[NEXP];
static __device__ int   g_token_ids[NASSIGN];          // row -> token
static __device__ int   g_pos_for[NASSIGN];            // (t,k) -> row
static __device__ int   g_top_idx[NASSIGN];
static __device__ float g_top_w[NASSIGN];

// ---------------- kernel: zero counters -----------------------------------
__global__ void zero_counts_kernel() {
    int i = threadIdx.x;
    if (i < NEXP) g_counts[i] = 0;
}

// ---------------- kernel: gating (1 block per token, 128 threads) ----------
__global__ void gate_kernel(const float* __restrict__ X,
                            const float* __restrict__ Wg,
                            const float* __restrict__ bg) {
    const int t   = blockIdx.x;
    const int tid = threadIdx.x;
    __shared__ float sm[NEXP][128];

    float acc[NEXP];
#pragma unroll
    for (int e = 0; e < NEXP; e++) acc[e] = 0.f;

    const float* x = X + (size_t)t * HDIM;
    for (int h = tid; h < HDIM; h += 128) {
        float xv = x[h];
        const float4* w4 = reinterpret_cast<const float4*>(Wg + (size_t)h * NEXP);
#pragma unroll
        for (int q = 0; q < 4; q++) {
            float4 w = w4[q];
            acc[q * 4 + 0] += xv * w.x;
            acc[q * 4 + 1] += xv * w.y;
            acc[q * 4 + 2] += xv * w.z;
            acc[q * 4 + 3] += xv * w.w;
        }
    }
#pragma unroll
    for (int e = 0; e < NEXP; e++) sm[e][tid] = acc[e];
    __syncthreads();
    for (int s = 64; s > 0; s >>= 1) {
        if (tid < s) {
#pragma unroll
            for (int e = 0; e < NEXP; e++) sm[e][tid] += sm[e][tid + s];
        }
        __syncthreads();
    }
    if (tid == 0) {
        float l[NEXP];
#pragma unroll
        for (int e = 0; e < NEXP; e++) l[e] = sm[e][0] + bg[e];
        // top-2 of logits (lowest index wins ties, matching jax top_k)
        int i0 = 0;
#pragma unroll
        for (int e = 1; e < NEXP; e++) if (l[e] > l[i0]) i0 = e;
        int i1 = (i0 == 0) ? 1 : 0;
#pragma unroll
        for (int e = 0; e < NEXP; e++) {
            if (e != i0 && l[e] > l[i1]) i1 = e;
        }
        // renormalized softmax over the two selected logits
        float e1 = __expf(l[i1] - l[i0]);
        float s  = 1.f + e1;
        float w0 = 1.f / s;
        float w1 = e1 / s;
        g_top_idx[2 * t + 0] = i0;  g_top_w[2 * t + 0] = w0;
        g_top_idx[2 * t + 1] = i1;  g_top_w[2 * t + 1] = w1;
        atomicAdd(&g_counts[i0], 1);
        atomicAdd(&g_counts[i1], 1);
    }
}

// ---------------- kernel: exclusive scan over 16 counts --------------------
__global__ void scan_kernel() {
    if (threadIdx.x == 0) {
        int off = 0;
        for (int e = 0; e < NEXP; e++) {
            g_offsets[e] = off;
            g_cursor[e]  = off;
            off += g_counts[e];
        }
    }
}

// ---------------- kernel: scatter assignments ------------------------------
// NOTE: atomic ordering permutes rows within an expert segment only. Each
// output row depends solely on its own token, so the final output is bitwise
// deterministic regardless of scatter order (graph-replay safe).
__global__ void scatter_kernel() {
    int idx = blockIdx.x * blockDim.x + threadIdx.x;
    if (idx >= NASSIGN) return;
    int t = idx >> 1;
    int e = g_top_idx[idx];
    int pos = atomicAdd(&g_cursor[e], 1);
    g_token_ids[pos] = t;
    g_pos_for[idx]   = pos;
}

// ---------------- grouped SGEMM 1: H = relu(gather(X) @ W1[e] + b1[e]) -----
// BM=BN=128, BK=8, 256 threads, 8x8 micro-tile, double-buffered smem.
__global__ __launch_bounds__(256) void gemm1_kernel(const float* __restrict__ X,
                                                    const float* __restrict__ W1,
                                                    const float* __restrict__ b1) {
    const int e    = blockIdx.z;
    const int ne   = g_counts[e];
    const int row0 = blockIdx.y * 128;
    if (row0 >= ne) return;
    const int off = g_offsets[e];
    const int n0  = blockIdx.x * 128;

    const float* __restrict__ Bw = W1 + (size_t)e * HDIM * MDIM;

    __shared__ float As[2][8][128];
    __shared__ float Bs[2][8][128];

    const int tid  = threadIdx.x;
    const int arow = tid >> 1;          // 0..127
    const int ak4  = (tid & 1) * 4;     // 0 or 4
    const int brow = tid >> 5;          // 0..7
    const int bcol = (tid & 31) * 4;    // 0..124
    const int tx   = tid & 15;
    const int ty   = tid >> 4;

    const int r      = row0 + arow;
    const bool avld  = (r < ne);
    const float* aptr = avld ? (X + (size_t)g_token_ids[off + r] * HDIM) : X;

    float acc[8][8];
#pragma unroll
    for (int i = 0; i < 8; i++)
#pragma unroll
        for (int j = 0; j < 8; j++) acc[i][j] = 0.f;

    // prologue: load tile 0
    float4 av = avld ? *reinterpret_cast<const float4*>(aptr + ak4)
                     : make_float4(0.f, 0.f, 0.f, 0.f);
    float4 bv = *reinterpret_cast<const float4*>(Bw + (size_t)brow * MDIM + n0 + bcol);
    As[0][ak4 + 0][arow] = av.x;
    As[0][ak4 + 1][arow] = av.y;
    As[0][ak4 + 2][arow] = av.z;
    As[0][ak4 + 3][arow] = av.w;
    *reinterpret_cast<float4*>(&Bs[0][brow][bcol]) = bv;
    __syncthreads();

    int buf = 0;
    for (int kk = 0; kk < HDIM; kk += 8) {
        const bool has_next = (kk + 8 < HDIM);
        if (has_next) {
            av = avld ? *reinterpret_cast<const float4*>(aptr + kk + 8 + ak4)
                      : make_float4(0.f, 0.f, 0.f, 0.f);
            bv = *reinterpret_cast<const float4*>(Bw + (size_t)(kk + 8 + brow) * MDIM + n0 + bcol);
        }
#pragma unroll
        for (int k = 0; k < 8; k++) {
            float4 a0 = *reinterpret_cast<const float4*>(&As[buf][k][ty * 8]);
            float4 a1 = *reinterpret_cast<const float4*>(&As[buf][k][ty * 8 + 4]);
            float4 b0 = *reinterpret_cast<const float4*>(&Bs[buf][k][tx * 8]);
            float4 b1v = *reinterpret_cast<const float4*>(&Bs[buf][k][tx * 8 + 4]);
            float a[8] = {a0.x, a0.y, a0.z, a0.w, a1.x, a1.y, a1.z, a1.w};
            float b[8] = {b0.x, b0.y, b0.z, b0.w, b1v.x, b1v.y, b1v.z, b1v.w};
#pragma unroll
            for (int i = 0; i < 8; i++)
#pragma unroll
                for (int j = 0; j < 8; j++) acc[i][j] += a[i] * b[j];
        }
        if (has_next) {
            int nb = buf ^ 1;
            As[nb][ak4 + 0][arow] = av.x;
            As[nb][ak4 + 1][arow] = av.y;
            As[nb][ak4 + 2][arow] = av.z;
            As[nb][ak4 + 3][arow] = av.w;
            *reinterpret_cast<float4*>(&Bs[nb][brow][bcol]) = bv;
            __syncthreads();
            buf = nb;
        }
    }

    // epilogue: +b1, relu, store to g_H
    const float* be = b1 + (size_t)e * MDIM + n0 + tx * 8;
    float bias[8];
#pragma unroll
    for (int j = 0; j < 8; j++) bias[j] = be[j];
#pragma unroll
    for (int i = 0; i < 8; i++) {
        int rr = row0 + ty * 8 + i;
        if (rr < ne) {
            float* hrow = g_H + (size_t)(off + rr) * MDIM + n0 + tx * 8;
            float4 v0, v1;
            v0.x = fmaxf(acc[i][0] + bias[0], 0.f);
            v0.y = fmaxf(acc[i][1] + bias[1], 0.f);
            v0.z = fmaxf(acc[i][2] + bias[2], 0.f);
            v0.w = fmaxf(acc[i][3] + bias[3], 0.f);
            v1.x = fmaxf(acc[i][4] + bias[4], 0.f);
            v1.y = fmaxf(acc[i][5] + bias[5], 0.f);
            v1.z = fmaxf(acc[i][6] + bias[6], 0.f);
            v1.w = fmaxf(acc[i][7] + bias[7], 0.f);
            *reinterpret_cast<float4*>(hrow)     = v0;
            *reinterpret_cast<float4*>(hrow + 4) = v1;
        }
    }
}

// ---------------- grouped SGEMM 2: Y = H @ W2[e] + b2[e] -------------------
__global__ __launch_bounds__(256) void gemm2_kernel(const float* __restrict__ W2,
                                                    const float* __restrict__ b2) {
    const int e    = blockIdx.z;
    const int ne   = g_counts[e];
    const int row0 = blockIdx.y * 128;
    if (row0 >= ne) return;
    const int off = g_offsets[e];
    const int n0  = blockIdx.x * 128;

    const float* __restrict__ Bw = W2 + (size_t)e * MDIM * HDIM;

    __shared__ float As[2][8][128];
    __shared__ float Bs[2][8][128];

    const int tid  = threadIdx.x;
    const int arow = tid >> 1;
    const int ak4  = (tid & 1) * 4;
    const int brow = tid >> 5;
    const int bcol = (tid & 31) * 4;
    const int tx   = tid & 15;
    const int ty   = tid >> 4;

    const int r     = row0 + arow;
    const bool avld = (r < ne);
    const float* aptr = avld ? (g_H + (size_t)(off + r) * MDIM) : g_H;

    float acc[8][8];
#pragma unroll
    for (int i = 0; i < 8; i++)
#pragma unroll
        for (int j = 0; j < 8; j++) acc[i][j] = 0.f;

    float4 av = avld ? *reinterpret_cast<const float4*>(aptr + ak4)
                     : make_float4(0.f, 0.f, 0.f, 0.f);
    float4 bv = *reinterpret_cast<const float4*>(Bw + (size_t)brow * HDIM + n0 + bcol);
    As[0][ak4 + 0][arow] = av.x;
    As[0][ak4 + 1][arow] = av.y;
    As[0][ak4 + 2][arow] = av.z;
    As[0][ak4 + 3][arow] = av.w;
    *reinterpret_cast<float4*>(&Bs[0][brow][bcol]) = bv;
    __syncthreads();

    int buf = 0;
    for (int kk = 0; kk < MDIM; kk += 8) {
        const bool has_next = (kk + 8 < MDIM);
        if (has_next) {
            av = avld ? *reinterpret_cast<const float4*>(aptr + kk + 8 + ak4)
                      : make_float4(0.f, 0.f, 0.f, 0.f);
            bv = *reinterpret_cast<const float4*>(Bw + (size_t)(kk + 8 + brow) * HDIM + n0 + bcol);
        }
#pragma unroll
        for (int k = 0; k < 8; k++) {
            float4 a0 = *reinterpret_cast<const float4*>(&As[buf][k][ty * 8]);
            float4 a1 = *reinterpret_cast<const float4*>(&As[buf][k][ty * 8 + 4]);
            float4 b0 = *reinterpret_cast<const float4*>(&Bs[buf][k][tx * 8]);
            float4 b1v = *reinterpret_cast<const float4*>(&Bs[buf][k][tx * 8 + 4]);
            float a[8] = {a0.x, a0.y, a0.z, a0.w, a1.x, a1.y, a1.z, a1.w};
            float b[8] = {b0.x, b0.y, b0.z, b0.w, b1v.x, b1v.y, b1v.z, b1v.w};
#pragma unroll
            for (int i = 0; i < 8; i++)
#pragma unroll
                for (int j = 0; j < 8; j++) acc[i][j] += a[i] * b[j];
        }
        if (has_next) {
            int nb = buf ^ 1;
            As[nb][ak4 + 0][arow] = av.x;
            As[nb][ak4 + 1][arow] = av.y;
            As[nb][ak4 + 2][arow] = av.z;
            As[nb][ak4 + 3][arow] = av.w;
            *reinterpret_cast<float4*>(&Bs[nb][brow][bcol]) = bv;
            __syncthreads();
            buf = nb;
        }
    }

    const float* be = b2 + (size_t)e * HDIM + n0 + tx * 8;
    float bias[8];
#pragma unroll
    for (int j = 0; j < 8; j++) bias[j] = be[j];
#pragma unroll
    for (int i = 0; i < 8; i++) {
        int rr = row0 + ty * 8 + i;
        if (rr < ne) {
            float* yrow = g_Y + (size_t)(off + rr) * HDIM + n0 + tx * 8;
            float4 v0, v1;
            v0.x = acc[i][0] + bias[0];
            v0.y = acc[i][1] + bias[1];
            v0.z = acc[i][2] + bias[2];
            v0.w = acc[i][3] + bias[3];
            v1.x = acc[i][4] + bias[4];
            v1.y = acc[i][5] + bias[5];
            v1.z = acc[i][6] + bias[6];
            v1.w = acc[i][7] + bias[7];
            *reinterpret_cast<float4*>(yrow)     = v0;
            *reinterpret_cast<float4*>(yrow + 4) = v1;
        }
    }
}

// ---------------- kernel: combine out[t] = w0*Y[p0] + w1*Y[p1] -------------
__global__ void combine_kernel(float* __restrict__ out) {
    const int t = blockIdx.x;
    const int p0 = g_pos_for[2 * t + 0];
    const int p1 = g_pos_for[2 * t + 1];
    const float w0 = g_top_w[2 * t + 0];
    const float w1 = g_top_w[2 * t + 1];
    const float4* y0 = reinterpret_cast<const float4*>(g_Y + (size_t)p0 * HDIM);
    const float4* y1 = reinterpret_cast<const float4*>(g_Y + (size_t)p1 * HDIM);
    float4* o = reinterpret_cast<float4*>(out + (size_t)t * HDIM);
    int n = threadIdx.x;  // 256 threads, 256 float4 = 1024 floats
    float4 a = y0[n];
    float4 b = y1[n];
    float4 v;
    v.x = w0 * a.x + w1 * b.x;
    v.y = w0 * a.y + w1 * b.y;
    v.z = w0 * a.z + w1 * b.z;
    v.w = w0 * a.w + w1 * b.w;
    o[n] = v;
}

// ---------------- launch ---------------------------------------------------
extern "C" void kernel_launch(void* const* d_in, const int* in_sizes, int n_in,
                              void* d_out, int out_size) {
    const float* X  = (const float*)d_in[0];
    const float* Wg = (const float*)d_in[1];
    const float* bg = (const float*)d_in[2];
    const float* W1 = (const float*)d_in[3];
    const float* b1 = (const float*)d_in[4];
    const float* W2 = (const float*)d_in[5];
    const float* b2 = (const float*)d_in[6];
    float* out = (float*)d_out;

    zero_counts_kernel<<<1, 32>>>();
    gate_kernel<<<T_TOK, 128>>>(X, Wg, bg);
    scan_kernel<<<1, 32>>>();
    scatter_kernel<<<(NASSIGN + 255) / 256, 256>>>();

    // GEMM1: N = MDIM = 2048 -> 16 col tiles; up to 256 row tiles; 16 experts
    dim3 g1(MDIM / 128, NASSIGN / 128, NEXP);
    gemm1_kernel<<<g1, 256>>>(X, W1, b1);

    // GEMM2: N = HDIM = 1024 -> 8 col tiles
    dim3 g2(HDIM / 128, NASSIGN / 128, NEXP);
    gemm2_kernel<<<g2, 256>>>(W2, b2);

    combine_kernel<<<T_TOK, 256>>>(out);
}

// round 13
// speedup vs baseline: 2.4860x; 2.4860x over previous
#include <cuda_runtime.h>
#include <cuda_fp16.h>
#include <math.h>
#include <stdint.h>

// Problem constants
#define T_TOK   16384
#define HDIM    1024
#define MDIM    2048
#define NEXP    16
#define NASSIGN (T_TOK * 2)     // 32768
#define MAX_TILES 272           // sum ceil(ne/128) <= 256 + 16
#define BK 32

// ---------------- scratch (device globals; no allocation allowed) ----------
static __device__ __half g_Xg_hi[(size_t)NASSIGN * HDIM];      // 64 MB
static __device__ __half g_Xg_lo[(size_t)NASSIGN * HDIM];      // 64 MB
static __device__ __half g_W1t_hi[(size_t)NEXP * MDIM * HDIM]; // 64 MB  [e][n][k]
static __device__ __half g_W1t_lo[(size_t)NEXP * MDIM * HDIM];
static __device__ __half g_W2t_hi[(size_t)NEXP * HDIM * MDIM]; // 64 MB  [e][n][k]
static __device__ __half g_W2t_lo[(size_t)NEXP * HDIM * MDIM];
static __device__ __half g_H_hi[(size_t)NASSIGN * MDIM];       // 128 MB
static __device__ __half g_H_lo[(size_t)NASSIGN * MDIM];
static __device__ float  g_Y[(size_t)NASSIGN * HDIM];          // 128 MB
static __device__ int    g_counts[NEXP];
static __device__ int    g_offsets[NEXP];
static __device__ int    g_cursor[NEXP];
static __device__ int    g_token_ids[NASSIGN];
static __device__ int    g_pos_for[NASSIGN];
static __device__ int    g_top_idx[NASSIGN];
static __device__ float  g_top_w[NASSIGN];
static __device__ int    g_tile_e[MAX_TILES];
static __device__ int    g_tile_row[MAX_TILES];
static __device__ int    g_tile_nr[MAX_TILES];
static __device__ int    g_ntiles;

// ---------------- PTX helpers (base sm_103 features only) -------------------
__device__ __forceinline__ uint32_t smem_u32(const void* p) {
    uint32_t a;
    asm("{ .reg .u64 t; cvta.to.shared.u64 t, %1; cvt.u32.u64 %0, t; }" : "=r"(a) : "l"(p));
    return a;
}

__device__ __forceinline__ void cp16(uint32_t saddr, const void* gaddr) {
    asm volatile("cp.async.cg.shared.global [%0], [%1], 16;" :: "r"(saddr), "l"(gaddr));
}
#define CP_COMMIT() asm volatile("cp.async.commit_group;")
#define CP_WAIT(n)  asm volatile("cp.async.wait_group %0;" :: "n"(n))

#define LDSM_X4(d0, d1, d2, d3, addr)                                       \
    asm volatile("ldmatrix.sync.aligned.m8n8.x4.shared.b16 {%0,%1,%2,%3}, [%4];" \
        : "=r"(d0), "=r"(d1), "=r"(d2), "=r"(d3) : "r"(addr))

__device__ __forceinline__ void mma16816(float* c, const uint32_t* a, const uint32_t* b) {
    asm volatile(
        "mma.sync.aligned.m16n8k16.row.col.f32.f16.f16.f32 "
        "{%0,%1,%2,%3}, {%4,%5,%6,%7}, {%8,%9}, {%0,%1,%2,%3};"
        : "+f"(c[0]), "+f"(c[1]), "+f"(c[2]), "+f"(c[3])
        : "r"(a[0]), "r"(a[1]), "r"(a[2]), "r"(a[3]), "r"(b[0]), "r"(b[1]));
}

// ---------------- small kernels ---------------------------------------------
__global__ void zero_counts_kernel() {
    int i = threadIdx.x;
    if (i < NEXP) g_counts[i] = 0;
}

__global__ void gate_kernel(const float* __restrict__ X,
                            const float* __restrict__ Wg,
                            const float* __restrict__ bg) {
    const int t   = blockIdx.x;
    const int tid = threadIdx.x;
    __shared__ float sm[NEXP][128];
    float acc[NEXP];
#pragma unroll
    for (int e = 0; e < NEXP; e++) acc[e] = 0.f;
    const float* x = X + (size_t)t * HDIM;
    for (int h = tid; h < HDIM; h += 128) {
        float xv = x[h];
        const float4* w4 = reinterpret_cast<const float4*>(Wg + (size_t)h * NEXP);
#pragma unroll
        for (int q = 0; q < 4; q++) {
            float4 w = w4[q];
            acc[q * 4 + 0] += xv * w.x;
            acc[q * 4 + 1] += xv * w.y;
            acc[q * 4 + 2] += xv * w.z;
            acc[q * 4 + 3] += xv * w.w;
        }
    }
#pragma unroll
    for (int e = 0; e < NEXP; e++) sm[e][tid] = acc[e];
    __syncthreads();
    for (int s = 64; s > 0; s >>= 1) {
        if (tid < s) {
#pragma unroll
            for (int e = 0; e < NEXP; e++) sm[e][tid] += sm[e][tid + s];
        }
        __syncthreads();
    }
    if (tid == 0) {
        float l[NEXP];
#pragma unroll
        for (int e = 0; e < NEXP; e++) l[e] = sm[e][0] + bg[e];
        int i0 = 0;
#pragma unroll
        for (int e = 1; e < NEXP; e++) if (l[e] > l[i0]) i0 = e;
        int i1 = (i0 == 0) ? 1 : 0;
#pragma unroll
        for (int e = 0; e < NEXP; e++) if (e != i0 && l[e] > l[i1]) i1 = e;
        float e1 = __expf(l[i1] - l[i0]);
        float s  = 1.f + e1;
        g_top_idx[2 * t + 0] = i0;  g_top_w[2 * t + 0] = 1.f / s;
        g_top_idx[2 * t + 1] = i1;  g_top_w[2 * t + 1] = e1 / s;
        atomicAdd(&g_counts[i0], 1);
        atomicAdd(&g_counts[i1], 1);
    }
}

__global__ void scan_kernel() {
    if (threadIdx.x == 0) {
        int off = 0;
        for (int e = 0; e < NEXP; e++) {
            g_offsets[e] = off;
            g_cursor[e]  = off;
            off += g_counts[e];
        }
        int nt = 0;
        for (int e = 0; e < NEXP; e++) {
            int ne = g_counts[e];
            for (int r = 0; r < ne; r += 128) {
                g_tile_e[nt]   = e;
                g_tile_row[nt] = g_offsets[e] + r;
                g_tile_nr[nt]  = (ne - r < 128) ? (ne - r) : 128;
                nt++;
            }
        }
        g_ntiles = nt;
    }
}

__global__ void scatter_kernel() {
    int idx = blockIdx.x * blockDim.x + threadIdx.x;
    if (idx >= NASSIGN) return;
    int t = idx >> 1;
    int e = g_top_idx[idx];
    int pos = atomicAdd(&g_cursor[e], 1);
    g_token_ids[pos] = t;
    g_pos_for[idx]   = pos;
}

// ---------------- conversion kernels ---------------------------------------
__device__ __forceinline__ void split_f16(float v, __half& h, __half& l) {
    h = __float2half_rn(v);
    l = __float2half_rn(v - __half2float(h));
}

__global__ void gather_convert_x(const float* __restrict__ X) {
    const int p = blockIdx.x;
    const int t = g_token_ids[p];
    const float4* src = reinterpret_cast<const float4*>(X + (size_t)t * HDIM);
    __half2* dh = reinterpret_cast<__half2*>(g_Xg_hi + (size_t)p * HDIM);
    __half2* dl = reinterpret_cast<__half2*>(g_Xg_lo + (size_t)p * HDIM);
    for (int c = threadIdx.x; c < HDIM / 4; c += blockDim.x) {
        float4 v = src[c];
        __half h0, h1, h2, h3, l0, l1, l2, l3;
        split_f16(v.x, h0, l0); split_f16(v.y, h1, l1);
        split_f16(v.z, h2, l2); split_f16(v.w, h3, l3);
        dh[c * 2]     = __halves2half2(h0, h1);
        dh[c * 2 + 1] = __halves2half2(h2, h3);
        dl[c * 2]     = __halves2half2(l0, l1);
        dl[c * 2 + 1] = __halves2half2(l2, l3);
    }
}

// W: [e][KD][ND] fp32 -> out [e][ND][KD] f16 hi/lo (K-major for MMA B operand)
template <int KD, int ND, bool IS_W1>
__global__ __launch_bounds__(256) void trans_convert(const float* __restrict__ W) {
    __shared__ float s[32][33];
    const int e  = blockIdx.z;
    const int k0 = blockIdx.y * 32;
    const int n0 = blockIdx.x * 32;
    const int tx = threadIdx.x & 31;
    const int ty = threadIdx.x >> 5;   // 0..7
    const float* Wp = W + (size_t)e * KD * ND;
#pragma unroll
    for (int i = 0; i < 4; i++) {
        int kr = ty + i * 8;
        s[kr][tx] = Wp[(size_t)(k0 + kr) * ND + n0 + tx];
    }
    __syncthreads();
    __half* oh = (IS_W1 ? g_W1t_hi : g_W2t_hi) + (size_t)e * ND * KD;
    __half* ol = (IS_W1 ? g_W1t_lo : g_W2t_lo) + (size_t)e * ND * KD;
#pragma unroll
    for (int i = 0; i < 4; i++) {
        int nr = ty + i * 8;
        float v = s[tx][nr];
        __half h, l;
        split_f16(v, h, l);
        oh[(size_t)(n0 + nr) * KD + k0 + tx] = h;
        ol[(size_t)(n0 + nr) * KD + k0 + tx] = l;
    }
}

// ---------------- warp-MMA grouped GEMM (mma.sync, base-target safe) --------
// BM=128, BN=128, BK=32. 256 threads = 8 warps, warp grid 4(m) x 2(n),
// warp tile 32x64. f16 hi/lo 3-term split, fp32 accum in registers.
// SMEM: 4 operand arrays (Ah, Al, Bh, Bl), each [2 stages][128 rows][40 halves]
// (pad 8 halves = 16B per row). 10240 B per array-stage; total 81920 B.
#define ROWH  40
#define STGB  10240
#define SMEM_BYTES 81920

template <int KTOT, int NOUT, bool IS_G1>
__global__ __launch_bounds__(256) void gemm_mma(const float* __restrict__ bias) {
    const int ti = blockIdx.y;
    if (ti >= g_ntiles) return;
    extern __shared__ char smem[];
    const uint32_t sb = smem_u32(smem);
    // byte bases: Ah | Al | Bh | Bl, each 2 stages of STGB
    const uint32_t AHB = sb;
    const uint32_t ALB = sb + 2 * STGB;
    const uint32_t BHB = sb + 4 * STGB;
    const uint32_t BLB = sb + 6 * STGB;

    const int tid  = threadIdx.x;
    const int lane = tid & 31;
    const int wid  = tid >> 5;
    const int wm   = wid >> 1;       // 0..3  (m offset wm*32)
    const int wn   = wid & 1;        // 0..1  (n offset wn*64)

    const int e     = g_tile_e[ti];
    const int row0  = g_tile_row[ti];
    const int nrows = g_tile_nr[ti];
    const int n0    = blockIdx.x * 128;
    const int bRow0 = e * NOUT + n0;

    const __half* __restrict__ Ahi = IS_G1 ? g_Xg_hi : g_H_hi;
    const __half* __restrict__ Alo = IS_G1 ? g_Xg_lo : g_H_lo;
    const __half* __restrict__ Bhi = IS_G1 ? g_W1t_hi : g_W2t_hi;
    const __half* __restrict__ Blo = IS_G1 ? g_W1t_lo : g_W2t_lo;

    // A-row gmem base (clamped for partial tiles; garbage rows masked on store)
    {
    }
    float acc[2][8][4];
#pragma unroll
    for (int i = 0; i < 2; i++)
#pragma unroll
        for (int j = 0; j < 8; j++)
#pragma unroll
            for (int q = 0; q < 4; q++) acc[i][j][q] = 0.f;

    auto load_stage = [&](int s, int b) {
        const int k0 = s * BK;
        const uint32_t ah = AHB + b * STGB;
        const uint32_t al = ALB + b * STGB;
        const uint32_t bh = BHB + b * STGB;
        const uint32_t bl = BLB + b * STGB;
#pragma unroll
        for (int i = 0; i < 2; i++) {                  // 512 16B chunks / 256 thr
            int m = tid + i * 256;
            int r = m >> 2, c = m & 3;
            int ar = row0 + r;
            if (ar >= NASSIGN) ar = NASSIGN - 1;
            size_t ago = (size_t)ar * KTOT + k0 + c * 8;
            size_t bgo = (size_t)(bRow0 + r) * KTOT + k0 + c * 8;
            uint32_t so = (uint32_t)(r * (ROWH * 2) + c * 16);
            cp16(ah + so, Ahi + ago);
            cp16(al + so, Alo + ago);
            cp16(bh + so, Bhi + bgo);
            cp16(bl + so, Blo + bgo);
        }
        CP_COMMIT();
    };

    constexpr int NST = KTOT / BK;
    load_stage(0, 0);
    load_stage(1, 1);

    for (int s = 0; s < NST; s++) {
        const int b = s & 1;
        if (s == NST - 1) { CP_WAIT(0); } else { CP_WAIT(1); }
        __syncthreads();

        const uint32_t ah = AHB + b * STGB;
        const uint32_t al = ALB + b * STGB;
        const uint32_t bh = BHB + b * STGB;
        const uint32_t bl = BLB + b * STGB;

#pragma unroll
        for (int kk = 0; kk < BK; kk += 16) {
            uint32_t ahf[2][4], alf[2][4], bhf[4][4], blf[4][4];
            // A fragments: two m16 tiles
            const uint32_t arow = (uint32_t)(wm * 32 + (lane & 15));
            const uint32_t akof = (uint32_t)((kk + ((lane >> 4) << 3)) * 2);
#pragma unroll
            for (int mt = 0; mt < 2; mt++) {
                uint32_t ad = ah + (arow + mt * 16) * (ROWH * 2) + akof;
                LDSM_X4(ahf[mt][0], ahf[mt][1], ahf[mt][2], ahf[mt][3], ad);
                uint32_t ad2 = al + (arow + mt * 16) * (ROWH * 2) + akof;
                LDSM_X4(alf[mt][0], alf[mt][1], alf[mt][2], alf[mt][3], ad2);
            }
            // B fragments: four n16 pairs (8 n8 tiles)
            const int g = lane >> 3;
            const uint32_t brow = (uint32_t)(wn * 64 + ((g >> 1) << 3) + (lane & 7));
            const uint32_t bkof = (uint32_t)((kk + ((g & 1) << 3)) * 2);
#pragma unroll
            for (int nt = 0; nt < 4; nt++) {
                uint32_t bd = bh + (brow + nt * 16) * (ROWH * 2) + bkof;
                LDSM_X4(bhf[nt][0], bhf[nt][1], bhf[nt][2], bhf[nt][3], bd);
                uint32_t bd2 = bl + (brow + nt * 16) * (ROWH * 2) + bkof;
                LDSM_X4(blf[nt][0], blf[nt][1], blf[nt][2], blf[nt][3], bd2);
            }
#pragma unroll
            for (int mt = 0; mt < 2; mt++) {
#pragma unroll
                for (int nb = 0; nb < 8; nb++) {
                    const uint32_t* bh2 = &bhf[nb >> 1][(nb & 1) * 2];
                    const uint32_t* bl2 = &blf[nb >> 1][(nb & 1) * 2];
                    mma16816(acc[mt][nb], ahf[mt], bh2);   // hi*hi
                    mma16816(acc[mt][nb], ahf[mt], bl2);   // hi*lo
                    mma16816(acc[mt][nb], alf[mt], bh2);   // lo*hi
                }
            }
        }
        __syncthreads();
        if (s + 2 < NST) load_stage(s + 2, b);
    }

    // epilogue. acc[mt][nb] = {c0,c1,c2,c3}: rows (lane>>2)+{0,8}, cols (lane&3)*2+{0,1}
    const float* bp = bias + (size_t)e * NOUT + n0;
#pragma unroll
    for (int mt = 0; mt < 2; mt++) {
#pragma unroll
        for (int half = 0; half < 2; half++) {
            const int r = wm * 32 + mt * 16 + (lane >> 2) + half * 8;
            if (r >= nrows) continue;
            const size_t orow = (size_t)(row0 + r);
#pragma unroll
            for (int nb = 0; nb < 8; nb++) {
                const int col = wn * 64 + nb * 8 + (lane & 3) * 2;
                float v0 = acc[mt][nb][half * 2 + 0] + bp[col];
                float v1 = acc[mt][nb][half * 2 + 1] + bp[col + 1];
                if (IS_G1) {
                    v0 = fmaxf(v0, 0.f);
                    v1 = fmaxf(v1, 0.f);
                    __half h0, l0, h1, l1;
                    split_f16(v0, h0, l0);
                    split_f16(v1, h1, l1);
                    *reinterpret_cast<__half2*>(g_H_hi + orow * NOUT + n0 + col) =
                        __halves2half2(h0, h1);
                    *reinterpret_cast<__half2*>(g_H_lo + orow * NOUT + n0 + col) =
                        __halves2half2(l0, l1);
                } else {
                    float2 v; v.x = v0; v.y = v1;
                    *reinterpret_cast<float2*>(g_Y + orow * NOUT + n0 + col) = v;
                }
            }
        }
    }
}

// ---------------- combine ---------------------------------------------------
__global__ void combine_kernel(float* __restrict__ out) {
    const int t  = blockIdx.x;
    const int p0 = g_pos_for[2 * t + 0];
    const int p1 = g_pos_for[2 * t + 1];
    const float w0 = g_top_w[2 * t + 0];
    const float w1 = g_top_w[2 * t + 1];
    const float4* y0 = reinterpret_cast<const float4*>(g_Y + (size_t)p0 * HDIM);
    const float4* y1 = reinterpret_cast<const float4*>(g_Y + (size_t)p1 * HDIM);
    float4* o = reinterpret_cast<float4*>(out + (size_t)t * HDIM);
    int n = threadIdx.x;
    float4 a = y0[n];
    float4 b = y1[n];
    float4 v;
    v.x = w0 * a.x + w1 * b.x;
    v.y = w0 * a.y + w1 * b.y;
    v.z = w0 * a.z + w1 * b.z;
    v.w = w0 * a.w + w1 * b.w;
    o[n] = v;
}

// ---------------- launch ----------------------------------------------------
extern "C" void kernel_launch(void* const* d_in, const int* in_sizes, int n_in,
                              void* d_out, int out_size) {
    const float* X  = (const float*)d_in[0];
    const float* Wg = (const float*)d_in[1];
    const float* bg = (const float*)d_in[2];
    const float* W1 = (const float*)d_in[3];
    const float* b1 = (const float*)d_in[4];
    const float* W2 = (const float*)d_in[5];
    const float* b2 = (const float*)d_in[6];
    float* out = (float*)d_out;

    cudaFuncSetAttribute((const void*)gemm_mma<HDIM, MDIM, true>,
                         cudaFuncAttributeMaxDynamicSharedMemorySize, SMEM_BYTES);
    cudaFuncSetAttribute((const void*)gemm_mma<MDIM, HDIM, false>,
                         cudaFuncAttributeMaxDynamicSharedMemorySize, SMEM_BYTES);

    zero_counts_kernel<<<1, 32>>>();
    gate_kernel<<<T_TOK, 128>>>(X, Wg, bg);
    scan_kernel<<<1, 32>>>();
    scatter_kernel<<<(NASSIGN + 255) / 256, 256>>>();

    gather_convert_x<<<NASSIGN, 128>>>(X);
    trans_convert<HDIM, MDIM, true ><<<dim3(MDIM / 32, HDIM / 32, NEXP), 256>>>(W1);
    trans_convert<MDIM, HDIM, false><<<dim3(HDIM / 32, MDIM / 32, NEXP), 256>>>(W2);

    // GEMM1: gathered X [*,1024] x W1t[e][2048,1024] -> H (relu, f16 hi/lo)
    gemm_mma<HDIM, MDIM, true ><<<dim3(MDIM / 128, MAX_TILES), 256, SMEM_BYTES>>>(b1);
    // GEMM2: H [*,2048] x W2t[e][1024,2048] -> Y (fp32)
    gemm_mma<MDIM, HDIM, false><<<dim3(HDIM / 128, MAX_TILES), 256, SMEM_BYTES>>>(b2);

    combine_kernel<<<T_TOK, 256>>>(out);
}

// round 14
// speedup vs baseline: 3.4061x; 1.3701x over previous
#include <cuda_runtime.h>
#include <cuda_fp16.h>
#include <math.h>
#include <stdint.h>

// Problem constants
#define T_TOK   16384
#define HDIM    1024
#define MDIM    2048
#define NEXP    16
#define NASSIGN (T_TOK * 2)     // 32768
#define MAX_TILES 272           // sum ceil(ne/128) <= 256 + 16
#define BK 32

// ---------------- scratch (device globals; no allocation allowed) ----------
static __device__ __half g_Xg_hi[(size_t)NASSIGN * HDIM];      // 64 MB
static __device__ __half g_Xg_lo[(size_t)NASSIGN * HDIM];      // 64 MB
static __device__ __half g_W1t[(size_t)NEXP * MDIM * HDIM];    // 64 MB  [e][n][k] f16
static __device__ __half g_W2t_hi[(size_t)NEXP * HDIM * MDIM]; // 64 MB  [e][n][k]
static __device__ __half g_W2t_lo[(size_t)NEXP * HDIM * MDIM]; // 64 MB
static __device__ __half g_H[(size_t)NASSIGN * MDIM];          // 128 MB (single f16)
static __device__ float  g_Y[(size_t)NASSIGN * HDIM];          // 128 MB
static __device__ int    g_counts[NEXP];
static __device__ int    g_offsets[NEXP];
static __device__ int    g_cursor[NEXP];
static __device__ int    g_token_ids[NASSIGN];
static __device__ int    g_pos_for[NASSIGN];
static __device__ int    g_top_idx[NASSIGN];
static __device__ float  g_top_w[NASSIGN];
static __device__ int    g_tile_e[MAX_TILES];
static __device__ int    g_tile_row[MAX_TILES];
static __device__ int    g_tile_nr[MAX_TILES];
static __device__ int    g_ntiles;

// ---------------- PTX helpers (base sm_103 features only) -------------------
__device__ __forceinline__ uint32_t smem_u32(const void* p) {
    uint32_t a;
    asm("{ .reg .u64 t; cvta.to.shared.u64 t, %1; cvt.u32.u64 %0, t; }" : "=r"(a) : "l"(p));
    return a;
}

__device__ __forceinline__ void cp16(uint32_t saddr, const void* gaddr) {
    asm volatile("cp.async.cg.shared.global [%0], [%1], 16;" :: "r"(saddr), "l"(gaddr));
}
#define CP_COMMIT() asm volatile("cp.async.commit_group;")
#define CP_WAIT(n)  asm volatile("cp.async.wait_group %0;" :: "n"(n))

#define LDSM_X4(d0, d1, d2, d3, addr)                                       \
    asm volatile("ldmatrix.sync.aligned.m8n8.x4.shared.b16 {%0,%1,%2,%3}, [%4];" \
        : "=r"(d0), "=r"(d1), "=r"(d2), "=r"(d3) : "r"(addr))

__device__ __forceinline__ void mma16816(float* c, const uint32_t* a, const uint32_t* b) {
    asm volatile(
        "mma.sync.aligned.m16n8k16.row.col.f32.f16.f16.f32 "
        "{%0,%1,%2,%3}, {%4,%5,%6,%7}, {%8,%9}, {%0,%1,%2,%3};"
        : "+f"(c[0]), "+f"(c[1]), "+f"(c[2]), "+f"(c[3])
        : "r"(a[0]), "r"(a[1]), "r"(a[2]), "r"(a[3]), "r"(b[0]), "r"(b[1]));
}

// ---------------- small kernels ---------------------------------------------
__global__ void zero_counts_kernel() {
    int i = threadIdx.x;
    if (i < NEXP) g_counts[i] = 0;
}

__global__ void gate_kernel(const float* __restrict__ X,
                            const float* __restrict__ Wg,
                            const float* __restrict__ bg) {
    const int t   = blockIdx.x;
    const int tid = threadIdx.x;
    __shared__ float sm[NEXP][128];
    float acc[NEXP];
#pragma unroll
    for (int e = 0; e < NEXP; e++) acc[e] = 0.f;
    const float* x = X + (size_t)t * HDIM;
    for (int h = tid; h < HDIM; h += 128) {
        float xv = x[h];
        const float4* w4 = reinterpret_cast<const float4*>(Wg + (size_t)h * NEXP);
#pragma unroll
        for (int q = 0; q < 4; q++) {
            float4 w = w4[q];
            acc[q * 4 + 0] += xv * w.x;
            acc[q * 4 + 1] += xv * w.y;
            acc[q * 4 + 2] += xv * w.z;
            acc[q * 4 + 3] += xv * w.w;
        }
    }
#pragma unroll
    for (int e = 0; e < NEXP; e++) sm[e][tid] = acc[e];
    __syncthreads();
    for (int s = 64; s > 0; s >>= 1) {
        if (tid < s) {
#pragma unroll
            for (int e = 0; e < NEXP; e++) sm[e][tid] += sm[e][tid + s];
        }
        __syncthreads();
    }
    if (tid == 0) {
        float l[NEXP];
#pragma unroll
        for (int e = 0; e < NEXP; e++) l[e] = sm[e][0] + bg[e];
        int i0 = 0;
#pragma unroll
        for (int e = 1; e < NEXP; e++) if (l[e] > l[i0]) i0 = e;
        int i1 = (i0 == 0) ? 1 : 0;
#pragma unroll
        for (int e = 0; e < NEXP; e++) if (e != i0 && l[e] > l[i1]) i1 = e;
        float e1 = __expf(l[i1] - l[i0]);
        float s  = 1.f + e1;
        g_top_idx[2 * t + 0] = i0;  g_top_w[2 * t + 0] = 1.f / s;
        g_top_idx[2 * t + 1] = i1;  g_top_w[2 * t + 1] = e1 / s;
        atomicAdd(&g_counts[i0], 1);
        atomicAdd(&g_counts[i1], 1);
    }
}

__global__ void scan_kernel() {
    if (threadIdx.x == 0) {
        int off = 0;
        for (int e = 0; e < NEXP; e++) {
            g_offsets[e] = off;
            g_cursor[e]  = off;
            off += g_counts[e];
        }
        int nt = 0;
        for (int e = 0; e < NEXP; e++) {
            int ne = g_counts[e];
            for (int r = 0; r < ne; r += 128) {
                g_tile_e[nt]   = e;
                g_tile_row[nt] = g_offsets[e] + r;
                g_tile_nr[nt]  = (ne - r < 128) ? (ne - r) : 128;
                nt++;
            }
        }
        g_ntiles = nt;
    }
}

__global__ void scatter_kernel() {
    int idx = blockIdx.x * blockDim.x + threadIdx.x;
    if (idx >= NASSIGN) return;
    int t = idx >> 1;
    int e = g_top_idx[idx];
    int pos = atomicAdd(&g_cursor[e], 1);
    g_token_ids[pos] = t;
    g_pos_for[idx]   = pos;
}

// ---------------- conversion kernels ---------------------------------------
__device__ __forceinline__ void split_f16(float v, __half& h, __half& l) {
    h = __float2half_rn(v);
    l = __float2half_rn(v - __half2float(h));
}

__global__ void gather_convert_x(const float* __restrict__ X) {
    const int p = blockIdx.x;
    const int t = g_token_ids[p];
    const float4* src = reinterpret_cast<const float4*>(X + (size_t)t * HDIM);
    __half2* dh = reinterpret_cast<__half2*>(g_Xg_hi + (size_t)p * HDIM);
    __half2* dl = reinterpret_cast<__half2*>(g_Xg_lo + (size_t)p * HDIM);
    for (int c = threadIdx.x; c < HDIM / 4; c += blockDim.x) {
        float4 v = src[c];
        __half h0, h1, h2, h3, l0, l1, l2, l3;
        split_f16(v.x, h0, l0); split_f16(v.y, h1, l1);
        split_f16(v.z, h2, l2); split_f16(v.w, h3, l3);
        dh[c * 2]     = __halves2half2(h0, h1);
        dh[c * 2 + 1] = __halves2half2(h2, h3);
        dl[c * 2]     = __halves2half2(l0, l1);
        dl[c * 2 + 1] = __halves2half2(l2, l3);
    }
}

// W: [e][KD][ND] fp32 -> [e][ND][KD] f16 (K-major).  SPLIT: also store lo.
template <int KD, int ND, bool SPLIT>
__global__ __launch_bounds__(256) void trans_convert(const float* __restrict__ W,
                                                     __half* __restrict__ out_hi,
                                                     __half* __restrict__ out_lo) {
    __shared__ float s[32][33];
    const int e  = blockIdx.z;
    const int k0 = blockIdx.y * 32;
    const int n0 = blockIdx.x * 32;
    const int tx = threadIdx.x & 31;
    const int ty = threadIdx.x >> 5;   // 0..7
    const float* Wp = W + (size_t)e * KD * ND;
#pragma unroll
    for (int i = 0; i < 4; i++) {
        int kr = ty + i * 8;
        s[kr][tx] = Wp[(size_t)(k0 + kr) * ND + n0 + tx];
    }
    __syncthreads();
    __half* oh = out_hi + (size_t)e * ND * KD;
    __half* ol = SPLIT ? (out_lo + (size_t)e * ND * KD) : nullptr;
#pragma unroll
    for (int i = 0; i < 4; i++) {
        int nr = ty + i * 8;
        float v = s[tx][nr];
        __half h, l;
        split_f16(v, h, l);
        oh[(size_t)(n0 + nr) * KD + k0 + tx] = h;
        if (SPLIT) ol[(size_t)(n0 + nr) * KD + k0 + tx] = l;
    }
}

// ---------------- warp-MMA grouped GEMM (2-term split) ----------------------
// BM=128, BN=128, BK=32. 256 threads = 8 warps, warp grid 4(m) x 2(n),
// warp tile 32x64. fp32 accum in registers.
// GEMM1 (IS_G1): A = X hi/lo (2 arrays), B = W1 f16.  acc += Ah*B + Al*B
// GEMM2        : A = H f16,  B = W2 hi/lo (2 arrays). acc += A*Bh + A*Bl
// SMEM: 3 operand arrays x [2 stages][128 rows][40 halves] = 61440 B.
#define ROWH  40
#define STGB  10240
#define SMEM_BYTES 61440

template <int KTOT, int NOUT, bool IS_G1>
__global__ __launch_bounds__(256) void gemm_mma(const float* __restrict__ bias) {
    const int ti = blockIdx.y;
    if (ti >= g_ntiles) return;
    extern __shared__ char smem[];
    const uint32_t sb = smem_u32(smem);
    const uint32_t AHB = sb;              // A hi
    const uint32_t EXB = sb + 2 * STGB;   // extra: A-lo (G1) or B-lo (G2)
    const uint32_t BHB = sb + 4 * STGB;   // B hi

    const int tid  = threadIdx.x;
    const int lane = tid & 31;
    const int wid  = tid >> 5;
    const int wm   = wid >> 1;       // 0..3  (m offset wm*32)
    const int wn   = wid & 1;        // 0..1  (n offset wn*64)

    const int e     = g_tile_e[ti];
    const int row0  = g_tile_row[ti];
    const int nrows = g_tile_nr[ti];
    const int n0    = blockIdx.x * 128;
    const int bRow0 = e * NOUT + n0;

    const __half* __restrict__ A0 = IS_G1 ? g_Xg_hi : g_H;
    const __half* __restrict__ A1 = IS_G1 ? g_Xg_lo : nullptr;
    const __half* __restrict__ B0 = IS_G1 ? g_W1t   : g_W2t_hi;
    const __half* __restrict__ B1 = IS_G1 ? nullptr : g_W2t_lo;

    float acc[2][8][4];
#pragma unroll
    for (int i = 0; i < 2; i++)
#pragma unroll
        for (int j = 0; j < 8; j++)
#pragma unroll
            for (int q = 0; q < 4; q++) acc[i][j][q] = 0.f;

    auto load_stage = [&](int s, int b) {
        const int k0 = s * BK;
        const uint32_t ah = AHB + b * STGB;
        const uint32_t ex = EXB + b * STGB;
        const uint32_t bh = BHB + b * STGB;
#pragma unroll
        for (int i = 0; i < 2; i++) {                  // 512 16B chunks / 256 thr
            int m = tid + i * 256;
            int r = m >> 2, c = m & 3;
            int ar = row0 + r;
            if (ar >= NASSIGN) ar = NASSIGN - 1;
            size_t ago = (size_t)ar * KTOT + k0 + c * 8;
            size_t bgo = (size_t)(bRow0 + r) * KTOT + k0 + c * 8;
            uint32_t so = (uint32_t)(r * (ROWH * 2) + c * 16);
            cp16(ah + so, A0 + ago);
            cp16(bh + so, B0 + bgo);
            if (IS_G1) cp16(ex + so, A1 + ago);
            else       cp16(ex + so, B1 + bgo);
        }
        CP_COMMIT();
    };

    constexpr int NST = KTOT / BK;
    load_stage(0, 0);
    load_stage(1, 1);

    for (int s = 0; s < NST; s++) {
        const int b = s & 1;
        if (s == NST - 1) { CP_WAIT(0); } else { CP_WAIT(1); }
        __syncthreads();

        const uint32_t ah = AHB + b * STGB;
        const uint32_t ex = EXB + b * STGB;
        const uint32_t bh = BHB + b * STGB;

#pragma unroll
        for (int kk = 0; kk < BK; kk += 16) {
            uint32_t ahf[2][4], aef[2][4], bhf[4][4], bef[4][4];
            // A fragments: two m16 tiles
            const uint32_t arow = (uint32_t)(wm * 32 + (lane & 15));
            const uint32_t akof = (uint32_t)((kk + ((lane >> 4) << 3)) * 2);
#pragma unroll
            for (int mt = 0; mt < 2; mt++) {
                uint32_t ad = ah + (arow + mt * 16) * (ROWH * 2) + akof;
                LDSM_X4(ahf[mt][0], ahf[mt][1], ahf[mt][2], ahf[mt][3], ad);
                if (IS_G1) {
                    uint32_t ad2 = ex + (arow + mt * 16) * (ROWH * 2) + akof;
                    LDSM_X4(aef[mt][0], aef[mt][1], aef[mt][2], aef[mt][3], ad2);
                }
            }
            // B fragments: four n16 pairs (8 n8 tiles)
            const int g = lane >> 3;
            const uint32_t brow = (uint32_t)(wn * 64 + ((g >> 1) << 3) + (lane & 7));
            const uint32_t bkof = (uint32_t)((kk + ((g & 1) << 3)) * 2);
#pragma unroll
            for (int nt = 0; nt < 4; nt++) {
                uint32_t bd = bh + (brow + nt * 16) * (ROWH * 2) + bkof;
                LDSM_X4(bhf[nt][0], bhf[nt][1], bhf[nt][2], bhf[nt][3], bd);
                if (!IS_G1) {
                    uint32_t bd2 = ex + (brow + nt * 16) * (ROWH * 2) + bkof;
                    LDSM_X4(bef[nt][0], bef[nt][1], bef[nt][2], bef[nt][3], bd2);
                }
            }
#pragma unroll
            for (int mt = 0; mt < 2; mt++) {
#pragma unroll
                for (int nb = 0; nb < 8; nb++) {
                    const uint32_t* b0 = &bhf[nb >> 1][(nb & 1) * 2];
                    mma16816(acc[mt][nb], ahf[mt], b0);            // hi * hi
                    if (IS_G1) {
                        mma16816(acc[mt][nb], aef[mt], b0);        // A-lo * B
                    } else {
                        const uint32_t* b1 = &bef[nb >> 1][(nb & 1) * 2];
                        mma16816(acc[mt][nb], ahf[mt], b1);        // A * B-lo
                    }
                }
            }
        }
        __syncthreads();
        if (s + 2 < NST) load_stage(s + 2, b);
    }

    // epilogue. acc[mt][nb] = {c0,c1,c2,c3}: rows (lane>>2)+{0,8}, cols (lane&3)*2+{0,1}
    const float* bp = bias + (size_t)e * NOUT + n0;
#pragma unroll
    for (int mt = 0; mt < 2; mt++) {
#pragma unroll
        for (int half = 0; half < 2; half++) {
            const int r = wm * 32 + mt * 16 + (lane >> 2) + half * 8;
            if (r >= nrows) continue;
            const size_t orow = (size_t)(row0 + r);
#pragma unroll
            for (int nb = 0; nb < 8; nb++) {
                const int col = wn * 64 + nb * 8 + (lane & 3) * 2;
                float v0 = acc[mt][nb][half * 2 + 0] + bp[col];
                float v1 = acc[mt][nb][half * 2 + 1] + bp[col + 1];
                if (IS_G1) {
                    v0 = fmaxf(v0, 0.f);
                    v1 = fmaxf(v1, 0.f);
                    *reinterpret_cast<__half2*>(g_H + orow * NOUT + n0 + col) =
                        __halves2half2(__float2half_rn(v0), __float2half_rn(v1));
                } else {
                    float2 v; v.x = v0; v.y = v1;
                    *reinterpret_cast<float2*>(g_Y + orow * NOUT + n0 + col) = v;
                }
            }
        }
    }
}

// ---------------- combine ---------------------------------------------------
__global__ void combine_kernel(float* __restrict__ out) {
    const int t  = blockIdx.x;
    const int p0 = g_pos_for[2 * t + 0];
    const int p1 = g_pos_for[2 * t + 1];
    const float w0 = g_top_w[2 * t + 0];
    const float w1 = g_top_w[2 * t + 1];
    const float4* y0 = reinterpret_cast<const float4*>(g_Y + (size_t)p0 * HDIM);
    const float4* y1 = reinterpret_cast<const float4*>(g_Y + (size_t)p1 * HDIM);
    float4* o = reinterpret_cast<float4*>(out + (size_t)t * HDIM);
    int n = threadIdx.x;
    float4 a = y0[n];
    float4 b = y1[n];
    float4 v;
    v.x = w0 * a.x + w1 * b.x;
    v.y = w0 * a.y + w1 * b.y;
    v.z = w0 * a.z + w1 * b.z;
    v.w = w0 * a.w + w1 * b.w;
    o[n] = v;
}

// ---------------- launch ----------------------------------------------------
extern "C" void kernel_launch(void* const* d_in, const int* in_sizes, int n_in,
                              void* d_out, int out_size) {
    const float* X  = (const float*)d_in[0];
    const float* Wg = (const float*)d_in[1];
    const float* bg = (const float*)d_in[2];
    const float* W1 = (const float*)d_in[3];
    const float* b1 = (const float*)d_in[4];
    const float* W2 = (const float*)d_in[5];
    const float* b2 = (const float*)d_in[6];
    float* out = (float*)d_out;

    cudaFuncSetAttribute((const void*)gemm_mma<HDIM, MDIM, true>,
                         cudaFuncAttributeMaxDynamicSharedMemorySize, SMEM_BYTES);
    cudaFuncSetAttribute((const void*)gemm_mma<MDIM, HDIM, false>,
                         cudaFuncAttributeMaxDynamicSharedMemorySize, SMEM_BYTES);

    zero_counts_kernel<<<1, 32>>>();
    gate_kernel<<<T_TOK, 128>>>(X, Wg, bg);
    scan_kernel<<<1, 32>>>();
    scatter_kernel<<<(NASSIGN + 255) / 256, 256>>>();

    gather_convert_x<<<NASSIGN, 128>>>(X);

    // device-symbol addresses are usable directly in device code; pass via kernel args
    {
        __half *w1h, *w2h, *w2l;
        cudaGetSymbolAddress((void**)&w1h, g_W1t);
        cudaGetSymbolAddress((void**)&w2h, g_W2t_hi);
        cudaGetSymbolAddress((void**)&w2l, g_W2t_lo);
        trans_convert<HDIM, MDIM, false><<<dim3(MDIM / 32, HDIM / 32, NEXP), 256>>>(W1, w1h, nullptr);
        trans_convert<MDIM, HDIM, true ><<<dim3(HDIM / 32, MDIM / 32, NEXP), 256>>>(W2, w2h, w2l);
    }

    // GEMM1: gathered X [*,1024] x W1t[e][2048,1024] -> H (relu, f16)
    gemm_mma<HDIM, MDIM, true ><<<dim3(MDIM / 128, MAX_TILES), 256, SMEM_BYTES>>>(b1);
    // GEMM2: H [*,2048] x W2t[e][1024,2048] (hi/lo) -> Y (fp32)
    gemm_mma<MDIM, HDIM, false><<<dim3(HDIM / 128, MAX_TILES), 256, SMEM_BYTES>>>(b2);

    combine_kernel<<<T_TOK, 256>>>(out);
}

// round 15
// speedup vs baseline: 5.5865x; 1.6401x over previous
#include <cuda_runtime.h>
#include <cuda_fp16.h>
#include <math.h>
#include <stdint.h>

// Problem constants
#define T_TOK   16384
#define HDIM    1024
#define MDIM    2048
#define NEXP    16
#define NASSIGN (T_TOK * 2)     // 32768
#define MAX_TILES 272           // sum ceil(ne/128) <= 256 + 16
#define BK 64

// ---------------- scratch (device globals; no allocation allowed) ----------
static __device__ __half g_Xg[(size_t)NASSIGN * HDIM];        // 64 MB gathered X f16
static __device__ __half g_W1t[(size_t)NEXP * MDIM * HDIM];   // 64 MB [e][n][k] f16
static __device__ __half g_W2t[(size_t)NEXP * HDIM * MDIM];   // 64 MB [e][n][k] f16
static __device__ __half g_H[(size_t)NASSIGN * MDIM];         // 128 MB f16
static __device__ float  g_Y[(size_t)NASSIGN * HDIM];         // 128 MB
static __device__ int    g_counts[NEXP];
static __device__ int    g_offsets[NEXP];
static __device__ int    g_cursor[NEXP];
static __device__ int    g_token_ids[NASSIGN];
static __device__ int    g_pos_for[NASSIGN];
static __device__ int    g_top_idx[NASSIGN];
static __device__ float  g_top_w[NASSIGN];
static __device__ int    g_tile_e[MAX_TILES];
static __device__ int    g_tile_row[MAX_TILES];
static __device__ int    g_tile_nr[MAX_TILES];
static __device__ int    g_ntiles;

// ---------------- PTX helpers (base sm_103 features only) -------------------
__device__ __forceinline__ uint32_t smem_u32(const void* p) {
    uint32_t a;
    asm("{ .reg .u64 t; cvta.to.shared.u64 t, %1; cvt.u32.u64 %0, t; }" : "=r"(a) : "l"(p));
    return a;
}

__device__ __forceinline__ void cp16(uint32_t saddr, const void* gaddr) {
    asm volatile("cp.async.cg.shared.global [%0], [%1], 16;" :: "r"(saddr), "l"(gaddr));
}
#define CP_COMMIT() asm volatile("cp.async.commit_group;")
#define CP_WAIT(n)  asm volatile("cp.async.wait_group %0;" :: "n"(n))

#define LDSM_X4(d0, d1, d2, d3, addr)                                       \
    asm volatile("ldmatrix.sync.aligned.m8n8.x4.shared.b16 {%0,%1,%2,%3}, [%4];" \
        : "=r"(d0), "=r"(d1), "=r"(d2), "=r"(d3) : "r"(addr))

__device__ __forceinline__ void mma16816(float* c, const uint32_t* a, const uint32_t* b) {
    asm volatile(
        "mma.sync.aligned.m16n8k16.row.col.f32.f16.f16.f32 "
        "{%0,%1,%2,%3}, {%4,%5,%6,%7}, {%8,%9}, {%0,%1,%2,%3};"
        : "+f"(c[0]), "+f"(c[1]), "+f"(c[2]), "+f"(c[3])
        : "r"(a[0]), "r"(a[1]), "r"(a[2]), "r"(a[3]), "r"(b[0]), "r"(b[1]));
}

// ---------------- small kernels ---------------------------------------------
__global__ void zero_counts_kernel() {
    int i = threadIdx.x;
    if (i < NEXP) g_counts[i] = 0;
}

__global__ void gate_kernel(const float* __restrict__ X,
                            const float* __restrict__ Wg,
                            const float* __restrict__ bg) {
    const int t   = blockIdx.x;
    const int tid = threadIdx.x;
    __shared__ float sm[NEXP][128];
    float acc[NEXP];
#pragma unroll
    for (int e = 0; e < NEXP; e++) acc[e] = 0.f;
    const float* x = X + (size_t)t * HDIM;
    for (int h = tid; h < HDIM; h += 128) {
        float xv = x[h];
        const float4* w4 = reinterpret_cast<const float4*>(Wg + (size_t)h * NEXP);
#pragma unroll
        for (int q = 0; q < 4; q++) {
            float4 w = w4[q];
            acc[q * 4 + 0] += xv * w.x;
            acc[q * 4 + 1] += xv * w.y;
            acc[q * 4 + 2] += xv * w.z;
            acc[q * 4 + 3] += xv * w.w;
        }
    }
#pragma unroll
    for (int e = 0; e < NEXP; e++) sm[e][tid] = acc[e];
    __syncthreads();
    for (int s = 64; s > 0; s >>= 1) {
        if (tid < s) {
#pragma unroll
            for (int e = 0; e < NEXP; e++) sm[e][tid] += sm[e][tid + s];
        }
        __syncthreads();
    }
    if (tid == 0) {
        float l[NEXP];
#pragma unroll
        for (int e = 0; e < NEXP; e++) l[e] = sm[e][0] + bg[e];
        int i0 = 0;
#pragma unroll
        for (int e = 1; e < NEXP; e++) if (l[e] > l[i0]) i0 = e;
        int i1 = (i0 == 0) ? 1 : 0;
#pragma unroll
        for (int e = 0; e < NEXP; e++) if (e != i0 && l[e] > l[i1]) i1 = e;
        float e1 = __expf(l[i1] - l[i0]);
        float s  = 1.f + e1;
        g_top_idx[2 * t + 0] = i0;  g_top_w[2 * t + 0] = 1.f / s;
        g_top_idx[2 * t + 1] = i1;  g_top_w[2 * t + 1] = e1 / s;
        atomicAdd(&g_counts[i0], 1);
        atomicAdd(&g_counts[i1], 1);
    }
}

__global__ void scan_kernel() {
    if (threadIdx.x == 0) {
        int off = 0;
        for (int e = 0; e < NEXP; e++) {
            g_offsets[e] = off;
            g_cursor[e]  = off;
            off += g_counts[e];
        }
        int nt = 0;
        for (int e = 0; e < NEXP; e++) {
            int ne = g_counts[e];
            for (int r = 0; r < ne; r += 128) {
                g_tile_e[nt]   = e;
                g_tile_row[nt] = g_offsets[e] + r;
                g_tile_nr[nt]  = (ne - r < 128) ? (ne - r) : 128;
                nt++;
            }
        }
        g_ntiles = nt;
    }
}

__global__ void scatter_kernel() {
    int idx = blockIdx.x * blockDim.x + threadIdx.x;
    if (idx >= NASSIGN) return;
    int t = idx >> 1;
    int e = g_top_idx[idx];
    int pos = atomicAdd(&g_cursor[e], 1);
    g_token_ids[pos] = t;
    g_pos_for[idx]   = pos;
}

// ---------------- conversion kernels ---------------------------------------
__global__ void gather_convert_x(const float* __restrict__ X) {
    const int p = blockIdx.x;
    const int t = g_token_ids[p];
    const float4* src = reinterpret_cast<const float4*>(X + (size_t)t * HDIM);
    __half2* dh = reinterpret_cast<__half2*>(g_Xg + (size_t)p * HDIM);
    for (int c = threadIdx.x; c < HDIM / 4; c += blockDim.x) {
        float4 v = src[c];
        dh[c * 2]     = __halves2half2(__float2half_rn(v.x), __float2half_rn(v.y));
        dh[c * 2 + 1] = __halves2half2(__float2half_rn(v.z), __float2half_rn(v.w));
    }
}

// W: [e][KD][ND] fp32 -> [e][ND][KD] f16 (K-major)
template <int KD, int ND>
__global__ __launch_bounds__(256) void trans_convert(const float* __restrict__ W,
                                                     __half* __restrict__ out) {
    __shared__ float s[32][33];
    const int e  = blockIdx.z;
    const int k0 = blockIdx.y * 32;
    const int n0 = blockIdx.x * 32;
    const int tx = threadIdx.x & 31;
    const int ty = threadIdx.x >> 5;   // 0..7
    const float* Wp = W + (size_t)e * KD * ND;
#pragma unroll
    for (int i = 0; i < 4; i++) {
        int kr = ty + i * 8;
        s[kr][tx] = Wp[(size_t)(k0 + kr) * ND + n0 + tx];
    }
    __syncthreads();
    __half* oh = out + (size_t)e * ND * KD;
#pragma unroll
    for (int i = 0; i < 4; i++) {
        int nr = ty + i * 8;
        oh[(size_t)(n0 + nr) * KD + k0 + tx] = __float2half_rn(s[tx][nr]);
    }
}

// ---------------- warp-MMA grouped GEMM (single f16) ------------------------
// BM=128, BN=128, BK=64. 256 threads = 8 warps, warp grid 4(m) x 2(n),
// warp tile 32x64. fp32 accum in registers.
// SMEM: A,B x [2 stages][128 rows][72 halves pad] = 4 x 18432 = 73728 B.
// Row stride 144 B -> 8 consecutive rows hit distinct 16B banks (conflict-free).
#define ROWH  72
#define STGB  18432
#define SMEM_BYTES 73728

template <int KTOT, int NOUT, bool IS_G1>
__global__ __launch_bounds__(256) void gemm_mma(const float* __restrict__ bias) {
    const int ti = blockIdx.y;
    if (ti >= g_ntiles) return;
    extern __shared__ char smem[];
    const uint32_t sb  = smem_u32(smem);
    const uint32_t ABase = sb;
    const uint32_t BBase = sb + 2 * STGB;

    const int tid  = threadIdx.x;
    const int lane = tid & 31;
    const int wid  = tid >> 5;
    const int wm   = wid >> 1;       // 0..3  (m offset wm*32)
    const int wn   = wid & 1;        // 0..1  (n offset wn*64)

    const int e     = g_tile_e[ti];
    const int row0  = g_tile_row[ti];
    const int nrows = g_tile_nr[ti];
    const int n0    = blockIdx.x * 128;
    const int bRow0 = e * NOUT + n0;

    const __half* __restrict__ A0 = IS_G1 ? g_Xg  : g_H;
    const __half* __restrict__ B0 = IS_G1 ? g_W1t : g_W2t;

    float acc[2][8][4];
#pragma unroll
    for (int i = 0; i < 2; i++)
#pragma unroll
        for (int j = 0; j < 8; j++)
#pragma unroll
            for (int q = 0; q < 4; q++) acc[i][j][q] = 0.f;

    auto load_stage = [&](int s, int b) {
        const int k0 = s * BK;
        const uint32_t ah = ABase + b * STGB;
        const uint32_t bh = BBase + b * STGB;
        // A: 128 rows x 64 halves = 1024 16B chunks; 4 per thread. Same for B.
#pragma unroll
        for (int i = 0; i < 4; i++) {
            int m = tid + i * 256;
            int r = m >> 3, c = m & 7;
            int ar = row0 + r;
            if (ar >= NASSIGN) ar = NASSIGN - 1;
            size_t ago = (size_t)ar * KTOT + k0 + c * 8;
            size_t bgo = (size_t)(bRow0 + r) * KTOT + k0 + c * 8;
            uint32_t so = (uint32_t)(r * (ROWH * 2) + c * 16);
            cp16(ah + so, A0 + ago);
            cp16(bh + so, B0 + bgo);
        }
        CP_COMMIT();
    };

    constexpr int NST = KTOT / BK;
    load_stage(0, 0);
    load_stage(1, 1);

    for (int s = 0; s < NST; s++) {
        const int b = s & 1;
        if (s == NST - 1) { CP_WAIT(0); } else { CP_WAIT(1); }
        __syncthreads();

        const uint32_t ah = ABase + b * STGB;
        const uint32_t bh = BBase + b * STGB;

#pragma unroll
        for (int kk = 0; kk < BK; kk += 16) {
            uint32_t af[2][4], bf[4][4];
            // A fragments: two m16 tiles
            const uint32_t arow = (uint32_t)(wm * 32 + (lane & 15));
            const uint32_t akof = (uint32_t)((kk + ((lane >> 4) << 3)) * 2);
#pragma unroll
            for (int mt = 0; mt < 2; mt++) {
                uint32_t ad = ah + (arow + mt * 16) * (ROWH * 2) + akof;
                LDSM_X4(af[mt][0], af[mt][1], af[mt][2], af[mt][3], ad);
            }
            // B fragments: four n16 pairs (8 n8 tiles)
            const int g = lane >> 3;
            const uint32_t brow = (uint32_t)(wn * 64 + ((g >> 1) << 3) + (lane & 7));
            const uint32_t bkof = (uint32_t)((kk + ((g & 1) << 3)) * 2);
#pragma unroll
            for (int nt = 0; nt < 4; nt++) {
                uint32_t bd = bh + (brow + nt * 16) * (ROWH * 2) + bkof;
                LDSM_X4(bf[nt][0], bf[nt][1], bf[nt][2], bf[nt][3], bd);
            }
#pragma unroll
            for (int mt = 0; mt < 2; mt++) {
#pragma unroll
                for (int nb = 0; nb < 8; nb++) {
                    mma16816(acc[mt][nb], af[mt], &bf[nb >> 1][(nb & 1) * 2]);
                }
            }
        }
        __syncthreads();
        if (s + 2 < NST) load_stage(s + 2, b);
    }

    // epilogue. acc[mt][nb] = {c0,c1,c2,c3}: rows (lane>>2)+{0,8}, cols (lane&3)*2+{0,1}
    const float* bp = bias + (size_t)e * NOUT + n0;
#pragma unroll
    for (int mt = 0; mt < 2; mt++) {
#pragma unroll
        for (int half = 0; half < 2; half++) {
            const int r = wm * 32 + mt * 16 + (lane >> 2) + half * 8;
            if (r >= nrows) continue;
            const size_t orow = (size_t)(row0 + r);
#pragma unroll
            for (int nb = 0; nb < 8; nb++) {
                const int col = wn * 64 + nb * 8 + (lane & 3) * 2;
                float v0 = acc[mt][nb][half * 2 + 0] + bp[col];
                float v1 = acc[mt][nb][half * 2 + 1] + bp[col + 1];
                if (IS_G1) {
                    v0 = fmaxf(v0, 0.f);
                    v1 = fmaxf(v1, 0.f);
                    *reinterpret_cast<__half2*>(g_H + orow * NOUT + n0 + col) =
                        __halves2half2(__float2half_rn(v0), __float2half_rn(v1));
                } else {
                    float2 v; v.x = v0; v.y = v1;
                    *reinterpret_cast<float2*>(g_Y + orow * NOUT + n0 + col) = v;
                }
            }
        }
    }
}

// ---------------- combine ---------------------------------------------------
__global__ void combine_kernel(float* __restrict__ out) {
    const int t  = blockIdx.x;
    const int p0 = g_pos_for[2 * t + 0];
    const int p1 = g_pos_for[2 * t + 1];
    const float w0 = g_top_w[2 * t + 0];
    const float w1 = g_top_w[2 * t + 1];
    const float4* y0 = reinterpret_cast<const float4*>(g_Y + (size_t)p0 * HDIM);
    const float4* y1 = reinterpret_cast<const float4*>(g_Y + (size_t)p1 * HDIM);
    float4* o = reinterpret_cast<float4*>(out + (size_t)t * HDIM);
    int n = threadIdx.x;
    float4 a = y0[n];
    float4 b = y1[n];
    float4 v;
    v.x = w0 * a.x + w1 * b.x;
    v.y = w0 * a.y + w1 * b.y;
    v.z = w0 * a.z + w1 * b.z;
    v.w = w0 * a.w + w1 * b.w;
    o[n] = v;
}

// ---------------- launch ----------------------------------------------------
extern "C" void kernel_launch(void* const* d_in, const int* in_sizes, int n_in,
                              void* d_out, int out_size) {
    const float* X  = (const float*)d_in[0];
    const float* Wg = (const float*)d_in[1];
    const float* bg = (const float*)d_in[2];
    const float* W1 = (const float*)d_in[3];
    const float* b1 = (const float*)d_in[4];
    const float* W2 = (const float*)d_in[5];
    const float* b2 = (const float*)d_in[6];
    float* out = (float*)d_out;

    cudaFuncSetAttribute((const void*)gemm_mma<HDIM, MDIM, true>,
                         cudaFuncAttributeMaxDynamicSharedMemorySize, SMEM_BYTES);
    cudaFuncSetAttribute((const void*)gemm_mma<MDIM, HDIM, false>,
                         cudaFuncAttributeMaxDynamicSharedMemorySize, SMEM_BYTES);

    zero_counts_kernel<<<1, 32>>>();
    gate_kernel<<<T_TOK, 128>>>(X, Wg, bg);
    scan_kernel<<<1, 32>>>();
    scatter_kernel<<<(NASSIGN + 255) / 256, 256>>>();

    gather_convert_x<<<NASSIGN, 128>>>(X);
    {
        __half *w1t, *w2t;
        cudaGetSymbolAddress((void**)&w1t, g_W1t);
        cudaGetSymbolAddress((void**)&w2t, g_W2t);
        trans_convert<HDIM, MDIM><<<dim3(MDIM / 32, HDIM / 32, NEXP), 256>>>(W1, w1t);
        trans_convert<MDIM, HDIM><<<dim3(HDIM / 32, MDIM / 32, NEXP), 256>>>(W2, w2t);
    }

    // GEMM1: gathered X [*,1024] x W1t[e][2048,1024] -> H (relu, f16)
    gemm_mma<HDIM, MDIM, true ><<<dim3(MDIM / 128, MAX_TILES), 256, SMEM_BYTES>>>(b1);
    // GEMM2: H [*,2048] x W2t[e][1024,2048] -> Y (fp32)
    gemm_mma<MDIM, HDIM, false><<<dim3(HDIM / 128, MAX_TILES), 256, SMEM_BYTES>>>(b2);

    combine_kernel<<<T_TOK, 256>>>(out);
}